// round 2
// baseline (speedup 1.0000x reference)
#include <cuda_runtime.h>

// Binarized-weight 3x3 conv, stride 1, pad 1.
// x: (32,128,64,64) f32 NCHW ; w: (256,128,3,3) f32 OIHW -> sign(w)
// out: (32,256,64,64) f32
//
// CTA tile: one image, 64 couts, 4 output rows, all 64 columns.
// ci tiled by 8. fp32 exact, packed fma.rn.f32x2 (2 output columns / instr).

#define CI_TILE 8
#define CO_TILE 64
#define H_TILE 4

__device__ __forceinline__ unsigned long long pk2(float lo, float hi) {
    unsigned long long r;
    asm("mov.b64 %0, {%1, %2};" : "=l"(r) : "f"(lo), "f"(hi));
    return r;
}
__device__ __forceinline__ unsigned long long fma2(unsigned long long a,
                                                   unsigned long long b,
                                                   unsigned long long c) {
    unsigned long long d;
    asm("fma.rn.f32x2 %0, %1, %2, %3;" : "=l"(d) : "l"(a), "l"(b), "l"(c));
    return d;
}
__device__ __forceinline__ void upk2(unsigned long long v, float& lo, float& hi) {
    asm("mov.b64 {%0, %1}, %2;" : "=f"(lo), "=f"(hi) : "l"(v));
}

__global__ __launch_bounds__(256, 2)
void bconv3x3_kernel(const float* __restrict__ x,
                     const float* __restrict__ w,
                     float* __restrict__ out)
{
    // x halo tile: CI_TILE x 6 rows x 66 valid cols (stride 68 for 8B alignment)
    __shared__ float xs[CI_TILE * 6 * 68];
    // binarized weights: [ci][co_local][k]  (k = kh*3+kw)
    __shared__ float sw[CI_TILE * CO_TILE * 9];

    const int n   = blockIdx.z;
    const int co0 = blockIdx.y * CO_TILE;
    const int h0  = blockIdx.x * H_TILE;

    const int t    = threadIdx.x;
    const int lw   = t & 31;     // 32 threads across width
    const int cg   = t >> 5;     // 8 cout groups of 8
    const int wcol = lw * 2;     // output columns (wcol, wcol+1)

    unsigned long long acc[8][4];
#pragma unroll
    for (int j = 0; j < 8; j++)
#pragma unroll
        for (int h = 0; h < 4; h++) acc[j][h] = 0ull;

    for (int cib = 0; cib < 128 / CI_TILE; cib++) {
        const int cbase = cib * CI_TILE;

        // ---- stage x halo tile (zero-padded borders) ----
        for (int i = t; i < CI_TILE * 6 * 66; i += 256) {
            int ci  = i / 396;          // 6*66
            int rem = i - ci * 396;
            int r   = rem / 66;
            int c   = rem - r * 66;
            int gh  = h0 - 1 + r;
            int gw  = c - 1;
            float v = 0.f;
            if ((unsigned)gh < 64u && (unsigned)gw < 64u)
                v = x[(((size_t)n * 128 + cbase + ci) * 64 + gh) * 64 + gw];
            xs[(ci * 6 + r) * 68 + c] = v;
        }
        // ---- stage binarized weights ----
        for (int i = t; i < CI_TILE * CO_TILE * 9; i += 256) {
            int ci  = i / (CO_TILE * 9);
            int rem = i - ci * (CO_TILE * 9);
            int col = rem / 9;
            int k   = rem - col * 9;
            float wv = w[(((size_t)(co0 + col)) * 128 + cbase + ci) * 9 + k];
            sw[i] = (wv > 0.f) ? 1.f : ((wv < 0.f) ? -1.f : 0.f);
        }
        __syncthreads();

#pragma unroll 1
        for (int ci = 0; ci < CI_TILE; ci++) {
#pragma unroll
            for (int kh = 0; kh < 3; kh++) {
                // x pairs for the 3 kw taps, 4 output rows
                unsigned long long p0[4], p1[4], p2[4];
#pragma unroll
                for (int h = 0; h < 4; h++) {
                    const float* row = &xs[(ci * 6 + kh + h) * 68 + wcol];
                    const float2 a = *(const float2*)(row);      // x[w],   x[w+1]
                    const float2 b = *(const float2*)(row + 2);  // x[w+2], x[w+3]
                    p0[h] = pk2(a.x, a.y);
                    p1[h] = pk2(a.y, b.x);
                    p2[h] = pk2(b.x, b.y);
                }
#pragma unroll
                for (int j = 0; j < 8; j++) {
                    const int base = (ci * CO_TILE + cg * 8 + j) * 9 + kh * 3;
                    const float s0 = sw[base];
                    const float s1 = sw[base + 1];
                    const float s2 = sw[base + 2];
                    const unsigned long long ss0 = pk2(s0, s0);
                    const unsigned long long ss1 = pk2(s1, s1);
                    const unsigned long long ss2 = pk2(s2, s2);
#pragma unroll
                    for (int h = 0; h < 4; h++) {
                        unsigned long long v = fma2(ss2, p2[h], acc[j][h]);
                        v = fma2(ss1, p1[h], v);
                        acc[j][h] = fma2(ss0, p0[h], v);
                    }
                }
            }
        }
        __syncthreads();
    }

    // ---- epilogue ----
#pragma unroll
    for (int j = 0; j < 8; j++) {
        const int co = co0 + cg * 8 + j;
#pragma unroll
        for (int h = 0; h < 4; h++) {
            float lo, hi;
            upk2(acc[j][h], lo, hi);
            float2* dst = (float2*)&out[(((size_t)n * 256 + co) * 64 + h0 + h) * 64 + wcol];
            *dst = make_float2(lo, hi);
        }
    }
}

extern "C" void kernel_launch(void* const* d_in, const int* in_sizes, int n_in,
                              void* d_out, int out_size)
{
    const float* x = (const float*)d_in[0];
    const float* w = (const float*)d_in[1];
    float* out = (float*)d_out;

    dim3 grid(64 / H_TILE /*16 h-blocks*/, 256 / CO_TILE /*4 co-blocks*/, 32 /*n*/);
    bconv3x3_kernel<<<grid, 256>>>(x, w, out);
}

// round 3
// speedup vs baseline: 1.0009x; 1.0009x over previous
#include <cuda_runtime.h>

// Binarized-weight 3x3 conv, stride 1, pad 1.
// x: (32,128,64,64) f32 NCHW ; w: (256,128,3,3) f32 OIHW -> sign(w)
// out: (32,256,64,64) f32
//
// CTA tile: one image, 64 couts, 4 output rows, all 64 columns.
// ci tiled by 8. fp32 exact, packed fma.rn.f32x2 (2 output columns / instr).

#define CI_TILE 8
#define CO_TILE 64
#define H_TILE 4

__device__ __forceinline__ unsigned long long pk2(float lo, float hi) {
    unsigned long long r;
    asm("mov.b64 %0, {%1, %2};" : "=l"(r) : "f"(lo), "f"(hi));
    return r;
}
__device__ __forceinline__ unsigned long long fma2(unsigned long long a,
                                                   unsigned long long b,
                                                   unsigned long long c) {
    unsigned long long d;
    asm("fma.rn.f32x2 %0, %1, %2, %3;" : "=l"(d) : "l"(a), "l"(b), "l"(c));
    return d;
}
__device__ __forceinline__ void upk2(unsigned long long v, float& lo, float& hi) {
    asm("mov.b64 {%0, %1}, %2;" : "=f"(lo), "=f"(hi) : "l"(v));
}

__global__ __launch_bounds__(256, 2)
void bconv3x3_kernel(const float* __restrict__ x,
                     const float* __restrict__ w,
                     float* __restrict__ out)
{
    // x halo tile: CI_TILE x 6 rows x 66 valid cols (stride 68 for 8B alignment)
    __shared__ float xs[CI_TILE * 6 * 68];
    // binarized weights: [ci][co_local][k]  (k = kh*3+kw)
    __shared__ float sw[CI_TILE * CO_TILE * 9];

    const int n   = blockIdx.z;
    const int co0 = blockIdx.y * CO_TILE;
    const int h0  = blockIdx.x * H_TILE;

    const int t    = threadIdx.x;
    const int lw   = t & 31;     // 32 threads across width
    const int cg   = t >> 5;     // 8 cout groups of 8
    const int wcol = lw * 2;     // output columns (wcol, wcol+1)

    unsigned long long acc[8][4];
#pragma unroll
    for (int j = 0; j < 8; j++)
#pragma unroll
        for (int h = 0; h < 4; h++) acc[j][h] = 0ull;

    for (int cib = 0; cib < 128 / CI_TILE; cib++) {
        const int cbase = cib * CI_TILE;

        // ---- stage x halo tile (zero-padded borders) ----
        for (int i = t; i < CI_TILE * 6 * 66; i += 256) {
            int ci  = i / 396;          // 6*66
            int rem = i - ci * 396;
            int r   = rem / 66;
            int c   = rem - r * 66;
            int gh  = h0 - 1 + r;
            int gw  = c - 1;
            float v = 0.f;
            if ((unsigned)gh < 64u && (unsigned)gw < 64u)
                v = x[(((size_t)n * 128 + cbase + ci) * 64 + gh) * 64 + gw];
            xs[(ci * 6 + r) * 68 + c] = v;
        }
        // ---- stage binarized weights ----
        for (int i = t; i < CI_TILE * CO_TILE * 9; i += 256) {
            int ci  = i / (CO_TILE * 9);
            int rem = i - ci * (CO_TILE * 9);
            int col = rem / 9;
            int k   = rem - col * 9;
            float wv = w[(((size_t)(co0 + col)) * 128 + cbase + ci) * 9 + k];
            sw[i] = (wv > 0.f) ? 1.f : ((wv < 0.f) ? -1.f : 0.f);
        }
        __syncthreads();

#pragma unroll 1
        for (int ci = 0; ci < CI_TILE; ci++) {
#pragma unroll
            for (int kh = 0; kh < 3; kh++) {
                // x pairs for the 3 kw taps, 4 output rows
                unsigned long long p0[4], p1[4], p2[4];
#pragma unroll
                for (int h = 0; h < 4; h++) {
                    const float* row = &xs[(ci * 6 + kh + h) * 68 + wcol];
                    const float2 a = *(const float2*)(row);      // x[w],   x[w+1]
                    const float2 b = *(const float2*)(row + 2);  // x[w+2], x[w+3]
                    p0[h] = pk2(a.x, a.y);
                    p1[h] = pk2(a.y, b.x);
                    p2[h] = pk2(b.x, b.y);
                }
#pragma unroll
                for (int j = 0; j < 8; j++) {
                    const int base = (ci * CO_TILE + cg * 8 + j) * 9 + kh * 3;
                    const float s0 = sw[base];
                    const float s1 = sw[base + 1];
                    const float s2 = sw[base + 2];
                    const unsigned long long ss0 = pk2(s0, s0);
                    const unsigned long long ss1 = pk2(s1, s1);
                    const unsigned long long ss2 = pk2(s2, s2);
#pragma unroll
                    for (int h = 0; h < 4; h++) {
                        unsigned long long v = fma2(ss2, p2[h], acc[j][h]);
                        v = fma2(ss1, p1[h], v);
                        acc[j][h] = fma2(ss0, p0[h], v);
                    }
                }
            }
        }
        __syncthreads();
    }

    // ---- epilogue ----
#pragma unroll
    for (int j = 0; j < 8; j++) {
        const int co = co0 + cg * 8 + j;
#pragma unroll
        for (int h = 0; h < 4; h++) {
            float lo, hi;
            upk2(acc[j][h], lo, hi);
            float2* dst = (float2*)&out[(((size_t)n * 256 + co) * 64 + h0 + h) * 64 + wcol];
            *dst = make_float2(lo, hi);
        }
    }
}

extern "C" void kernel_launch(void* const* d_in, const int* in_sizes, int n_in,
                              void* d_out, int out_size)
{
    const float* x = (const float*)d_in[0];
    const float* w = (const float*)d_in[1];
    float* out = (float*)d_out;

    dim3 grid(64 / H_TILE /*16 h-blocks*/, 256 / CO_TILE /*4 co-blocks*/, 32 /*n*/);
    bconv3x3_kernel<<<grid, 256>>>(x, w, out);
}

// round 4
// speedup vs baseline: 1.0010x; 1.0001x over previous
#include <cuda_runtime.h>

// Binarized-weight 3x3 conv, stride 1, pad 1.
// x: (32,128,64,64) f32 NCHW ; w: (256,128,3,3) f32 OIHW -> sign(w)
// out: (32,256,64,64) f32
//
// CTA tile: one image, 64 couts, 4 output rows, all 64 columns.
// ci tiled by 8. fp32 exact, packed fma.rn.f32x2 (2 output columns / instr).

#define CI_TILE 8
#define CO_TILE 64
#define H_TILE 4

__device__ __forceinline__ unsigned long long pk2(float lo, float hi) {
    unsigned long long r;
    asm("mov.b64 %0, {%1, %2};" : "=l"(r) : "f"(lo), "f"(hi));
    return r;
}
__device__ __forceinline__ unsigned long long fma2(unsigned long long a,
                                                   unsigned long long b,
                                                   unsigned long long c) {
    unsigned long long d;
    asm("fma.rn.f32x2 %0, %1, %2, %3;" : "=l"(d) : "l"(a), "l"(b), "l"(c));
    return d;
}
__device__ __forceinline__ void upk2(unsigned long long v, float& lo, float& hi) {
    asm("mov.b64 {%0, %1}, %2;" : "=f"(lo), "=f"(hi) : "l"(v));
}

__global__ __launch_bounds__(256, 2)
void bconv3x3_kernel(const float* __restrict__ x,
                     const float* __restrict__ w,
                     float* __restrict__ out)
{
    // x halo tile: CI_TILE x 6 rows x 66 valid cols (stride 68 for 8B alignment)
    __shared__ float xs[CI_TILE * 6 * 68];
    // binarized weights: [ci][co_local][k]  (k = kh*3+kw)
    __shared__ float sw[CI_TILE * CO_TILE * 9];

    const int n   = blockIdx.z;
    const int co0 = blockIdx.y * CO_TILE;
    const int h0  = blockIdx.x * H_TILE;

    const int t    = threadIdx.x;
    const int lw   = t & 31;     // 32 threads across width
    const int cg   = t >> 5;     // 8 cout groups of 8
    const int wcol = lw * 2;     // output columns (wcol, wcol+1)

    unsigned long long acc[8][4];
#pragma unroll
    for (int j = 0; j < 8; j++)
#pragma unroll
        for (int h = 0; h < 4; h++) acc[j][h] = 0ull;

    for (int cib = 0; cib < 128 / CI_TILE; cib++) {
        const int cbase = cib * CI_TILE;

        // ---- stage x halo tile (zero-padded borders) ----
        for (int i = t; i < CI_TILE * 6 * 66; i += 256) {
            int ci  = i / 396;          // 6*66
            int rem = i - ci * 396;
            int r   = rem / 66;
            int c   = rem - r * 66;
            int gh  = h0 - 1 + r;
            int gw  = c - 1;
            float v = 0.f;
            if ((unsigned)gh < 64u && (unsigned)gw < 64u)
                v = x[(((size_t)n * 128 + cbase + ci) * 64 + gh) * 64 + gw];
            xs[(ci * 6 + r) * 68 + c] = v;
        }
        // ---- stage binarized weights ----
        for (int i = t; i < CI_TILE * CO_TILE * 9; i += 256) {
            int ci  = i / (CO_TILE * 9);
            int rem = i - ci * (CO_TILE * 9);
            int col = rem / 9;
            int k   = rem - col * 9;
            float wv = w[(((size_t)(co0 + col)) * 128 + cbase + ci) * 9 + k];
            sw[i] = (wv > 0.f) ? 1.f : ((wv < 0.f) ? -1.f : 0.f);
        }
        __syncthreads();

#pragma unroll 1
        for (int ci = 0; ci < CI_TILE; ci++) {
#pragma unroll
            for (int kh = 0; kh < 3; kh++) {
                // x pairs for the 3 kw taps, 4 output rows
                unsigned long long p0[4], p1[4], p2[4];
#pragma unroll
                for (int h = 0; h < 4; h++) {
                    const float* row = &xs[(ci * 6 + kh + h) * 68 + wcol];
                    const float2 a = *(const float2*)(row);      // x[w],   x[w+1]
                    const float2 b = *(const float2*)(row + 2);  // x[w+2], x[w+3]
                    p0[h] = pk2(a.x, a.y);
                    p1[h] = pk2(a.y, b.x);
                    p2[h] = pk2(b.x, b.y);
                }
#pragma unroll
                for (int j = 0; j < 8; j++) {
                    const int base = (ci * CO_TILE + cg * 8 + j) * 9 + kh * 3;
                    const float s0 = sw[base];
                    const float s1 = sw[base + 1];
                    const float s2 = sw[base + 2];
                    const unsigned long long ss0 = pk2(s0, s0);
                    const unsigned long long ss1 = pk2(s1, s1);
                    const unsigned long long ss2 = pk2(s2, s2);
#pragma unroll
                    for (int h = 0; h < 4; h++) {
                        unsigned long long v = fma2(ss2, p2[h], acc[j][h]);
                        v = fma2(ss1, p1[h], v);
                        acc[j][h] = fma2(ss0, p0[h], v);
                    }
                }
            }
        }
        __syncthreads();
    }

    // ---- epilogue ----
#pragma unroll
    for (int j = 0; j < 8; j++) {
        const int co = co0 + cg * 8 + j;
#pragma unroll
        for (int h = 0; h < 4; h++) {
            float lo, hi;
            upk2(acc[j][h], lo, hi);
            float2* dst = (float2*)&out[(((size_t)n * 256 + co) * 64 + h0 + h) * 64 + wcol];
            *dst = make_float2(lo, hi);
        }
    }
}

extern "C" void kernel_launch(void* const* d_in, const int* in_sizes, int n_in,
                              void* d_out, int out_size)
{
    const float* x = (const float*)d_in[0];
    const float* w = (const float*)d_in[1];
    float* out = (float*)d_out;

    dim3 grid(64 / H_TILE /*16 h-blocks*/, 256 / CO_TILE /*4 co-blocks*/, 32 /*n*/);
    bconv3x3_kernel<<<grid, 256>>>(x, w, out);
}

// round 6
// speedup vs baseline: 4.3201x; 4.3156x over previous
#include <cuda_runtime.h>
#include <cuda_bf16.h>
#include <cstdint>

// ============================================================================
// Binarized-weight 3x3 conv, stride 1, pad 1, via implicit GEMM on HMMA
// (mma.sync m16n8k16 bf16 — arch-neutral PTX, works at compute_103 target).
// x: (32,128,64,64) f32 NCHW ; w: (256,128,3,3) f32 OIHW -> sign(w) ; out f32.
//
// out[p, co] = sum_{chunk,tap,ci} sign(W) * x[ci, p + shift(tap)]
// over padded flattened pixel space (66x66 per image), bf16 hi/lo split for
// fp32-grade accuracy.
// ============================================================================

#define NPOS_STRIDE 4736ull   // 128 guard + pixels + tail guard
#define POS_BASE    128
#define N_TILES     35        // ceil(66*66 / 128) = 35 tiles of 128 positions
#define HALO        72        // rows of lead guard inside the A smem halo
#define A_ROWS      272       // 128 tile + 67 lead + 67 tail (+ pad)

// -------- scratch (zero-initialized device globals; guards stay 0) ----------
__device__ __nv_bfloat16 g_xhi[32ull * NPOS_STRIDE * 128];
__device__ __nv_bfloat16 g_xlo[32ull * NPOS_STRIDE * 128];
__device__ __nv_bfloat16 g_wb[2 * 9 * 256 * 64];   // [chunk][tap][co][ci64]

// ---------------------------- helpers ---------------------------------------
__device__ __forceinline__ uint32_t smem_u32(const void* p) {
    uint32_t a;
    asm("{ .reg .u64 t; cvta.to.shared.u64 t, %1; cvt.u32.u64 %0, t; }"
        : "=r"(a) : "l"(p));
    return a;
}

__device__ __forceinline__ void ldsm_x4(uint32_t& r0, uint32_t& r1,
                                        uint32_t& r2, uint32_t& r3,
                                        uint32_t addr) {
    asm volatile("ldmatrix.sync.aligned.m8n8.x4.shared.b16 {%0,%1,%2,%3}, [%4];"
                 : "=r"(r0), "=r"(r1), "=r"(r2), "=r"(r3) : "r"(addr));
}

__device__ __forceinline__ void mma_bf16(float* c, const uint32_t* a,
                                         uint32_t b0, uint32_t b1) {
    asm volatile(
        "mma.sync.aligned.m16n8k16.row.col.f32.bf16.bf16.f32 "
        "{%0,%1,%2,%3}, {%4,%5,%6,%7}, {%8,%9}, {%0,%1,%2,%3};"
        : "+f"(c[0]), "+f"(c[1]), "+f"(c[2]), "+f"(c[3])
        : "r"(a[0]), "r"(a[1]), "r"(a[2]), "r"(a[3]), "r"(b0), "r"(b1));
}

// ---------------------------- pre-kernel: weights ----------------------------
__global__ void __launch_bounds__(256) prep_w(const float* __restrict__ w) {
    int idx = blockIdx.x * 256 + threadIdx.x;   // [co][ci][tap] flat
    if (idx >= 256 * 128 * 9) return;
    int co  = idx / 1152;
    int rem = idx - co * 1152;
    int ci  = rem / 9;
    int tap = rem - ci * 9;
    float v = w[idx];
    float s = (v > 0.f) ? 1.f : ((v < 0.f) ? -1.f : 0.f);
    g_wb[(((ci >> 6) * 9 + tap) << 14) + (co << 6) + (ci & 63)] = __float2bfloat16_rn(s);
}

// ------------------- pre-kernel: pad + transpose + split x -------------------
__global__ void __launch_bounds__(256) prep_x(const float* __restrict__ x) {
    __shared__ float st[64 * 129];
    const int h = blockIdx.x, n = blockIdx.y, t = threadIdx.x;

    for (int idx = t; idx < 8192; idx += 256) {
        int ci = idx >> 6, w = idx & 63;
        st[w * 129 + ci] = x[(((size_t)n * 128 + ci) * 64 + h) * 64 + w];
    }
    __syncthreads();
    for (int idx = t; idx < 8192; idx += 256) {
        int w = idx >> 7, ci = idx & 127;
        float v = st[w * 129 + ci];
        __nv_bfloat16 hi = __float2bfloat16_rn(v);
        __nv_bfloat16 lo = __float2bfloat16_rn(v - __bfloat162float(hi));
        size_t pos = (size_t)n * NPOS_STRIDE + POS_BASE + (size_t)(h + 1) * 66 + (w + 1);
        g_xhi[pos * 128 + ci] = hi;
        g_xlo[pos * 128 + ci] = lo;
    }
}

// ------------------------------- main kernel ---------------------------------
// dynamic smem layout (bytes):
//   A_hi : [0,      34816)   272 rows x 128B, swizzled
//   A_lo : [34816,  69632)
//   B    : [69632,  86016)   128 rows x 128B, swizzled
//   D (epilogue, reuses A): 128co x 132 floats = 67584B
#define SM_AHI   0
#define SM_ALO   34816
#define SM_B     69632
#define SM_TOTAL 86016

__global__ void __launch_bounds__(256, 2)
bconv_hmma(float* __restrict__ out) {
    extern __shared__ char sm[];
    const uint32_t smb = smem_u32(sm);

    const int t    = threadIdx.x;
    const int wid  = t >> 5;
    const int lane = t & 31;
    const int n    = blockIdx.z;
    const int coB  = blockIdx.y;           // 0/1 -> co block of 128
    const int p0   = blockIdx.x * 128;

    const int mw = wid & 1;                // 2 m-halves of 64 pix
    const int nw = wid >> 1;               // 4 n-quarters of 32 co

    // lane-invariant ldmatrix offsets
    const int q  = lane >> 3;
    const int rA = (lane & 7) + ((q & 1) << 3);     // A row-in-tile
    const int cA = q >> 1;                          // A k-half (16B unit)
    const int rB = (lane & 7) + ((lane >> 4) << 3); // B row-in-pair
    const int cB = q & 1;                           // B k-half

    float acc[4][4][4];
#pragma unroll
    for (int i = 0; i < 4; i++)
#pragma unroll
        for (int j = 0; j < 4; j++)
#pragma unroll
            for (int k = 0; k < 4; k++) acc[i][j][k] = 0.f;

    // element offset of halo row 0 (ci0 of current image)
    const size_t xrow0 = ((size_t)n * NPOS_STRIDE + POS_BASE + p0 - HALO) * 128;

#pragma unroll 1
    for (int chunk = 0; chunk < 2; chunk++) {
        __syncthreads();   // previous chunk's compute done before A overwrite

        // ---- load A halo: 272 rows x 64 ci, hi + lo, swizzled ----
        for (int i = t; i < A_ROWS * 8; i += 256) {
            const int r = i >> 3, j = i & 7;
            const size_t gsrc = xrow0 + (size_t)r * 128 + (chunk << 6) + (j << 3);
            const uint32_t doff = (uint32_t)(r * 128 + (((j ^ (r & 7)) << 4)));
            *(uint4*)(sm + SM_AHI + doff) = *(const uint4*)(g_xhi + gsrc);
            *(uint4*)(sm + SM_ALO + doff) = *(const uint4*)(g_xlo + gsrc);
        }

#pragma unroll 1
        for (int tap = 0; tap < 9; tap++) {
            __syncthreads();   // prior tap done reading B (first tap: A stores visible)

            // ---- load B tile: 128 co x 64 ci, swizzled ----
            {
                const __nv_bfloat16* src =
                    g_wb + ((chunk * 9 + tap) << 14) + ((coB * 128) << 6);
                for (int i = t; i < 128 * 8; i += 256) {
                    const int r = i >> 3, j = i & 7;
                    const uint32_t doff = (uint32_t)(r * 128 + ((j ^ (r & 7)) << 4));
                    *(uint4*)(sm + SM_B + doff) = *(const uint4*)(src + (i << 3));
                }
            }
            __syncthreads();

            const int s = (tap / 3 - 1) * 66 + (tap % 3 - 1);
            const int aRowBase = mw * 64 + s + HALO;
            const int bRowBase = nw * 32;

#pragma unroll
            for (int ks = 0; ks < 4; ks++) {
                // B frags: 4 n8-tiles via 2 ldmatrix.x4
                uint32_t bf[4][2];
#pragma unroll
                for (int pr = 0; pr < 2; pr++) {
                    const int row = bRowBase + pr * 16 + rB;
                    const uint32_t addr = smb + SM_B + row * 128 +
                                          (((2 * ks + cB) ^ (row & 7)) << 4);
                    ldsm_x4(bf[pr * 2][0], bf[pr * 2][1],
                            bf[pr * 2 + 1][0], bf[pr * 2 + 1][1], addr);
                }
                // A_hi frags + mma
                uint32_t af[4][4];
#pragma unroll
                for (int mt = 0; mt < 4; mt++) {
                    const int row = aRowBase + mt * 16 + rA;
                    const uint32_t addr = smb + SM_AHI + row * 128 +
                                          (((2 * ks + cA) ^ (row & 7)) << 4);
                    ldsm_x4(af[mt][0], af[mt][1], af[mt][2], af[mt][3], addr);
                }
#pragma unroll
                for (int mt = 0; mt < 4; mt++)
#pragma unroll
                    for (int nt = 0; nt < 4; nt++)
                        mma_bf16(acc[mt][nt], af[mt], bf[nt][0], bf[nt][1]);
                // A_lo frags + mma
#pragma unroll
                for (int mt = 0; mt < 4; mt++) {
                    const int row = aRowBase + mt * 16 + rA;
                    const uint32_t addr = smb + SM_ALO + row * 128 +
                                          (((2 * ks + cA) ^ (row & 7)) << 4);
                    ldsm_x4(af[mt][0], af[mt][1], af[mt][2], af[mt][3], addr);
                }
#pragma unroll
                for (int mt = 0; mt < 4; mt++)
#pragma unroll
                    for (int nt = 0; nt < 4; nt++)
                        mma_bf16(acc[mt][nt], af[mt], bf[nt][0], bf[nt][1]);
            }
        }
    }

    // ---- epilogue: acc -> smem D [co][132] -> coalesced masked gmem stores ----
    __syncthreads();
    float* D = (float*)sm;
    const int gRow = lane >> 2;
    const int gCol = (lane & 3) * 2;
#pragma unroll
    for (int mt = 0; mt < 4; mt++) {
#pragma unroll
        for (int nt = 0; nt < 4; nt++) {
            const int pl  = mw * 64 + mt * 16 + gRow;
            const int col = nw * 32 + nt * 8 + gCol;
            D[col * 132 + pl]           = acc[mt][nt][0];
            D[(col + 1) * 132 + pl]     = acc[mt][nt][1];
            D[col * 132 + pl + 8]       = acc[mt][nt][2];
            D[(col + 1) * 132 + pl + 8] = acc[mt][nt][3];
        }
    }
    __syncthreads();

    for (int i = t; i < 128 * 128; i += 256) {
        const int co_l = i >> 7, p_l = i & 127;
        const int p  = p0 + p_l;
        const int hp = p / 66;
        const int wp = p - hp * 66;
        if (hp >= 1 && hp <= 64 && wp >= 1 && wp <= 64)
            out[(((size_t)n * 256 + coB * 128 + co_l) << 12) +
                ((hp - 1) << 6) + (wp - 1)] = D[co_l * 132 + p_l];
    }
}

// ------------------------------- launcher ------------------------------------
extern "C" void kernel_launch(void* const* d_in, const int* in_sizes, int n_in,
                              void* d_out, int out_size) {
    const float* x = (const float*)d_in[0];
    const float* w = (const float*)d_in[1];
    float* out = (float*)d_out;

    cudaFuncSetAttribute(bconv_hmma, cudaFuncAttributeMaxDynamicSharedMemorySize,
                         SM_TOTAL);

    prep_w<<<1152, 256>>>(w);
    prep_x<<<dim3(64, 32), 256>>>(x);
    bconv_hmma<<<dim3(N_TILES, 2, 32), 256, SM_TOTAL>>>(out);
}

// round 7
// speedup vs baseline: 5.3198x; 1.2314x over previous
#include <cuda_runtime.h>
#include <cuda_bf16.h>
#include <cstdint>

// ============================================================================
// Binarized-weight 3x3 conv, stride 1, pad 1, via implicit GEMM on HMMA
// (mma.sync m16n8k16 bf16 — arch-neutral PTX, works at compute_103 target).
// x: (32,128,64,64) f32 NCHW ; w: (256,128,3,3) f32 OIHW -> sign(w) ; out f32.
//
// out[p, co] = sum_{chunk,tap,ci} sign(W) * x[ci, p + shift(tap)]
// over padded flattened pixel space (66x66 per image), bf16 hi/lo split for
// fp32-grade accuracy. This round: cp.async pipeline, double-buffered B.
// ============================================================================

#define NPOS_STRIDE 4736ull   // 128 guard + pixels + tail guard
#define POS_BASE    128
#define N_TILES     35        // ceil(66*66 / 128) = 35 tiles of 128 positions
#define HALO        72        // rows of lead guard inside the A smem halo
#define A_ROWS      272       // covers shifts [-67,+67] around 128-row tile

// -------- scratch (zero-initialized device globals; guards stay 0) ----------
__device__ __nv_bfloat16 g_xhi[32ull * NPOS_STRIDE * 128];
__device__ __nv_bfloat16 g_xlo[32ull * NPOS_STRIDE * 128];
__device__ __nv_bfloat16 g_wb[2 * 9 * 256 * 64];   // [chunk][tap][co][ci64]

// ---------------------------- helpers ---------------------------------------
__device__ __forceinline__ uint32_t smem_u32(const void* p) {
    uint32_t a;
    asm("{ .reg .u64 t; cvta.to.shared.u64 t, %1; cvt.u32.u64 %0, t; }"
        : "=r"(a) : "l"(p));
    return a;
}

#define CP_ASYNC16(dst_u32, src_ptr) \
    asm volatile("cp.async.cg.shared.global [%0], [%1], 16;" \
                 :: "r"(dst_u32), "l"(src_ptr))
#define CP_COMMIT() asm volatile("cp.async.commit_group;" ::: "memory")
#define CP_WAIT0()  asm volatile("cp.async.wait_group 0;" ::: "memory")

__device__ __forceinline__ void ldsm_x4(uint32_t& r0, uint32_t& r1,
                                        uint32_t& r2, uint32_t& r3,
                                        uint32_t addr) {
    asm volatile("ldmatrix.sync.aligned.m8n8.x4.shared.b16 {%0,%1,%2,%3}, [%4];"
                 : "=r"(r0), "=r"(r1), "=r"(r2), "=r"(r3) : "r"(addr));
}

__device__ __forceinline__ void mma_bf16(float* c, const uint32_t* a,
                                         uint32_t b0, uint32_t b1) {
    asm volatile(
        "mma.sync.aligned.m16n8k16.row.col.f32.bf16.bf16.f32 "
        "{%0,%1,%2,%3}, {%4,%5,%6,%7}, {%8,%9}, {%0,%1,%2,%3};"
        : "+f"(c[0]), "+f"(c[1]), "+f"(c[2]), "+f"(c[3])
        : "r"(a[0]), "r"(a[1]), "r"(a[2]), "r"(a[3]), "r"(b0), "r"(b1));
}

// ---------------------------- pre-kernel: weights ----------------------------
__global__ void __launch_bounds__(256) prep_w(const float* __restrict__ w) {
    int idx = blockIdx.x * 256 + threadIdx.x;   // [co][ci][tap] flat
    if (idx >= 256 * 128 * 9) return;
    int co  = idx / 1152;
    int rem = idx - co * 1152;
    int ci  = rem / 9;
    int tap = rem - ci * 9;
    float v = w[idx];
    float s = (v > 0.f) ? 1.f : ((v < 0.f) ? -1.f : 0.f);
    g_wb[(((ci >> 6) * 9 + tap) << 14) + (co << 6) + (ci & 63)] = __float2bfloat16_rn(s);
}

// ------------------- pre-kernel: pad + transpose + split x -------------------
__global__ void __launch_bounds__(256) prep_x(const float* __restrict__ x) {
    __shared__ float st[64 * 129];
    const int h = blockIdx.x, n = blockIdx.y, t = threadIdx.x;

    for (int idx = t; idx < 8192; idx += 256) {
        int ci = idx >> 6, w = idx & 63;
        st[w * 129 + ci] = x[(((size_t)n * 128 + ci) * 64 + h) * 64 + w];
    }
    __syncthreads();
    for (int idx = t; idx < 8192; idx += 256) {
        int w = idx >> 7, ci = idx & 127;
        float v = st[w * 129 + ci];
        __nv_bfloat16 hi = __float2bfloat16_rn(v);
        __nv_bfloat16 lo = __float2bfloat16_rn(v - __bfloat162float(hi));
        size_t pos = (size_t)n * NPOS_STRIDE + POS_BASE + (size_t)(h + 1) * 66 + (w + 1);
        g_xhi[pos * 128 + ci] = hi;
        g_xlo[pos * 128 + ci] = lo;
    }
}

// ------------------------------- main kernel ---------------------------------
// dynamic smem layout (bytes):
//   A_hi : [0,      34816)   272 rows x 128B, swizzled
//   A_lo : [34816,  69632)
//   B0   : [69632,  86016)   128 rows x 128B, swizzled (double-buffered)
//   B1   : [86016, 102400)
//   D (epilogue, reuses A): 128co x 132 floats = 67584B
#define SM_AHI   0
#define SM_ALO   34816
#define SM_B0    69632
#define SM_B1    86016
#define SM_TOTAL 102400

__global__ void __launch_bounds__(256, 2)
bconv_hmma(float* __restrict__ out) {
    extern __shared__ char sm[];
    const uint32_t smb = smem_u32(sm);

    const int t    = threadIdx.x;
    const int wid  = t >> 5;
    const int lane = t & 31;
    const int n    = blockIdx.z;
    const int coB  = blockIdx.y;           // 0/1 -> co block of 128
    const int p0   = blockIdx.x * 128;

    const int mw = wid & 1;                // 2 m-halves of 64 pix
    const int nw = wid >> 1;               // 4 n-quarters of 32 co

    // lane-invariant ldmatrix offsets
    const int q  = lane >> 3;
    const int rA = (lane & 7) + ((q & 1) << 3);     // A row-in-tile
    const int cA = q >> 1;                          // A k-half (16B unit)
    const int rB = (lane & 7) + ((lane >> 4) << 3); // B row-in-pair
    const int cB = q & 1;                          // B k-half

    float acc[4][4][4];
#pragma unroll
    for (int i = 0; i < 4; i++)
#pragma unroll
        for (int j = 0; j < 4; j++)
#pragma unroll
            for (int k = 0; k < 4; k++) acc[i][j][k] = 0.f;

    // element offset of halo row 0 (ci0 of current image)
    const size_t xrow0 = ((size_t)n * NPOS_STRIDE + POS_BASE + p0 - HALO) * 128;
    const __nv_bfloat16* wbase = g_wb + (coB << 13);   // co block offset

    // ---- prologue: prefetch B(iter 0) ----
    {
        const __nv_bfloat16* src = wbase;              // chunk 0, tap 0
        for (int i = t; i < 1024; i += 256) {
            const int r = i >> 3, j = i & 7;
            const uint32_t doff = (uint32_t)(r * 128 + ((j ^ (r & 7)) << 4));
            CP_ASYNC16(smb + SM_B0 + doff, src + (i << 3));
        }
        CP_COMMIT();
    }

#pragma unroll 1
    for (int iter = 0; iter < 18; ++iter) {
        const int chunk = iter / 9;
        const int tap   = iter - chunk * 9;

        if (tap == 0) {
            __syncthreads();   // everyone done reading old A halo
            // ---- cp.async A halo: 272 rows x 64 ci, hi + lo, swizzled ----
            for (int i = t; i < A_ROWS * 8; i += 256) {
                const int r = i >> 3, j = i & 7;
                const size_t gsrc = xrow0 + (size_t)r * 128 + (chunk << 6) + (j << 3);
                const uint32_t doff = (uint32_t)(r * 128 + ((j ^ (r & 7)) << 4));
                CP_ASYNC16(smb + SM_AHI + doff, g_xhi + gsrc);
                CP_ASYNC16(smb + SM_ALO + doff, g_xlo + gsrc);
            }
            CP_COMMIT();
        }

        CP_WAIT0();            // A (this chunk) + B (this iter) landed
        __syncthreads();       // also frees the other B buffer for prefetch

        if (iter < 17) {       // ---- prefetch next iter's B ----
            const int ni = iter + 1;
            const int nc = ni / 9;
            const __nv_bfloat16* src = wbase + (((nc * 9 + (ni - nc * 9)) << 14));
            const uint32_t bdst = smb + ((ni & 1) ? SM_B1 : SM_B0);
            for (int i = t; i < 1024; i += 256) {
                const int r = i >> 3, j = i & 7;
                const uint32_t doff = (uint32_t)(r * 128 + ((j ^ (r & 7)) << 4));
                CP_ASYNC16(bdst + doff, src + (i << 3));
            }
            CP_COMMIT();
        }

        // ---- compute tap ----
        const int s = (tap / 3 - 1) * 66 + (tap % 3 - 1);
        const int aRowBase = mw * 64 + s + HALO;
        const int bRowBase = nw * 32;
        const uint32_t bbase = smb + ((iter & 1) ? SM_B1 : SM_B0);

#pragma unroll
        for (int ks = 0; ks < 4; ks++) {
            uint32_t bf[4][2];
#pragma unroll
            for (int pr = 0; pr < 2; pr++) {
                const int row = bRowBase + pr * 16 + rB;
                const uint32_t addr = bbase + row * 128 +
                                      (((2 * ks + cB) ^ (row & 7)) << 4);
                ldsm_x4(bf[pr * 2][0], bf[pr * 2][1],
                        bf[pr * 2 + 1][0], bf[pr * 2 + 1][1], addr);
            }
            uint32_t af[4][4];
#pragma unroll
            for (int mt = 0; mt < 4; mt++) {
                const int row = aRowBase + mt * 16 + rA;
                const uint32_t addr = smb + SM_AHI + row * 128 +
                                      (((2 * ks + cA) ^ (row & 7)) << 4);
                ldsm_x4(af[mt][0], af[mt][1], af[mt][2], af[mt][3], addr);
            }
#pragma unroll
            for (int mt = 0; mt < 4; mt++)
#pragma unroll
                for (int nt = 0; nt < 4; nt++)
                    mma_bf16(acc[mt][nt], af[mt], bf[nt][0], bf[nt][1]);
#pragma unroll
            for (int mt = 0; mt < 4; mt++) {
                const int row = aRowBase + mt * 16 + rA;
                const uint32_t addr = smb + SM_ALO + row * 128 +
                                      (((2 * ks + cA) ^ (row & 7)) << 4);
                ldsm_x4(af[mt][0], af[mt][1], af[mt][2], af[mt][3], addr);
            }
#pragma unroll
            for (int mt = 0; mt < 4; mt++)
#pragma unroll
                for (int nt = 0; nt < 4; nt++)
                    mma_bf16(acc[mt][nt], af[mt], bf[nt][0], bf[nt][1]);
        }
    }

    // ---- epilogue: acc -> smem D [co][132] -> coalesced masked gmem stores ----
    __syncthreads();
    float* D = (float*)sm;
    const int gRow = lane >> 2;
    const int gCol = (lane & 3) * 2;
#pragma unroll
    for (int mt = 0; mt < 4; mt++) {
#pragma unroll
        for (int nt = 0; nt < 4; nt++) {
            const int pl  = mw * 64 + mt * 16 + gRow;
            const int col = nw * 32 + nt * 8 + gCol;
            D[col * 132 + pl]           = acc[mt][nt][0];
            D[(col + 1) * 132 + pl]     = acc[mt][nt][1];
            D[col * 132 + pl + 8]       = acc[mt][nt][2];
            D[(col + 1) * 132 + pl + 8] = acc[mt][nt][3];
        }
    }
    __syncthreads();

    for (int i = t; i < 128 * 128; i += 256) {
        const int co_l = i >> 7, p_l = i & 127;
        const int p  = p0 + p_l;
        const int hp = p / 66;
        const int wp = p - hp * 66;
        if (hp >= 1 && hp <= 64 && wp >= 1 && wp <= 64)
            out[(((size_t)n * 256 + coB * 128 + co_l) << 12) +
                ((hp - 1) << 6) + (wp - 1)] = D[co_l * 132 + p_l];
    }
}

// ------------------------------- launcher ------------------------------------
extern "C" void kernel_launch(void* const* d_in, const int* in_sizes, int n_in,
                              void* d_out, int out_size) {
    const float* x = (const float*)d_in[0];
    const float* w = (const float*)d_in[1];
    float* out = (float*)d_out;

    cudaFuncSetAttribute(bconv_hmma, cudaFuncAttributeMaxDynamicSharedMemorySize,
                         SM_TOTAL);

    prep_w<<<1152, 256>>>(w);
    prep_x<<<dim3(64, 32), 256>>>(x);
    bconv_hmma<<<dim3(N_TILES, 2, 32), 256, SM_TOTAL>>>(out);
}

// round 8
// speedup vs baseline: 8.5399x; 1.6053x over previous
#include <cuda_runtime.h>
#include <cuda_fp16.h>
#include <cstdint>

// ============================================================================
// Binarized-weight 3x3 conv, stride 1, pad 1, via implicit GEMM on HMMA
// (mma.sync m16n8k16 fp16 -> fp32 accum; arch-neutral PTX at compute_103).
// x: (32,128,64,64) f32 NCHW ; w: (256,128,3,3) f32 OIHW -> sign(w) ; out f32.
//
// out[p, co] = sum_{chunk,tap,ci} sign(W) * x[ci, p + shift(tap)]
// over padded flattened pixel space (66x66 per image). Single-pass fp16:
// per-term quantization 2^-12..2^-11 -> output rel_err ~1e-4 (<1e-3 threshold).
// cp.async pipeline with double-buffered B (structure from round 7).
// ============================================================================

#define NPOS_STRIDE 4736ull   // 128 guard + pixels + tail guard
#define POS_BASE    128
#define N_TILES     35        // ceil(66*66 / 128) = 35 tiles of 128 positions
#define HALO        72        // rows of lead guard inside the A smem halo
#define A_ROWS      272       // covers shifts [-67,+67] around 128-row tile

// -------- scratch (zero-initialized device globals; guards stay 0) ----------
__device__ __half g_xh[32ull * NPOS_STRIDE * 128];
__device__ __half g_wb[2 * 9 * 256 * 64];   // [chunk][tap][co][ci64]

// ---------------------------- helpers ---------------------------------------
__device__ __forceinline__ uint32_t smem_u32(const void* p) {
    uint32_t a;
    asm("{ .reg .u64 t; cvta.to.shared.u64 t, %1; cvt.u32.u64 %0, t; }"
        : "=r"(a) : "l"(p));
    return a;
}

#define CP_ASYNC16(dst_u32, src_ptr) \
    asm volatile("cp.async.cg.shared.global [%0], [%1], 16;" \
                 :: "r"(dst_u32), "l"(src_ptr))
#define CP_COMMIT() asm volatile("cp.async.commit_group;" ::: "memory")
#define CP_WAIT0()  asm volatile("cp.async.wait_group 0;" ::: "memory")

__device__ __forceinline__ void ldsm_x4(uint32_t& r0, uint32_t& r1,
                                        uint32_t& r2, uint32_t& r3,
                                        uint32_t addr) {
    asm volatile("ldmatrix.sync.aligned.m8n8.x4.shared.b16 {%0,%1,%2,%3}, [%4];"
                 : "=r"(r0), "=r"(r1), "=r"(r2), "=r"(r3) : "r"(addr));
}

__device__ __forceinline__ void mma_f16(float* c, const uint32_t* a,
                                        uint32_t b0, uint32_t b1) {
    asm volatile(
        "mma.sync.aligned.m16n8k16.row.col.f32.f16.f16.f32 "
        "{%0,%1,%2,%3}, {%4,%5,%6,%7}, {%8,%9}, {%0,%1,%2,%3};"
        : "+f"(c[0]), "+f"(c[1]), "+f"(c[2]), "+f"(c[3])
        : "r"(a[0]), "r"(a[1]), "r"(a[2]), "r"(a[3]), "r"(b0), "r"(b1));
}

// ---------------------------- pre-kernel: weights ----------------------------
__global__ void __launch_bounds__(256) prep_w(const float* __restrict__ w) {
    int idx = blockIdx.x * 256 + threadIdx.x;   // [co][ci][tap] flat
    if (idx >= 256 * 128 * 9) return;
    int co  = idx / 1152;
    int rem = idx - co * 1152;
    int ci  = rem / 9;
    int tap = rem - ci * 9;
    float v = w[idx];
    float s = (v > 0.f) ? 1.f : ((v < 0.f) ? -1.f : 0.f);
    g_wb[(((ci >> 6) * 9 + tap) << 14) + (co << 6) + (ci & 63)] = __float2half_rn(s);
}

// ------------------- pre-kernel: pad + transpose x (fp16) --------------------
__global__ void __launch_bounds__(256) prep_x(const float* __restrict__ x) {
    __shared__ float st[64 * 129];
    const int h = blockIdx.x, n = blockIdx.y, t = threadIdx.x;

    for (int idx = t; idx < 8192; idx += 256) {
        int ci = idx >> 6, w = idx & 63;
        st[w * 129 + ci] = x[(((size_t)n * 128 + ci) * 64 + h) * 64 + w];
    }
    __syncthreads();
    for (int idx = t; idx < 8192; idx += 256) {
        int w = idx >> 7, ci = idx & 127;
        size_t pos = (size_t)n * NPOS_STRIDE + POS_BASE + (size_t)(h + 1) * 66 + (w + 1);
        g_xh[pos * 128 + ci] = __float2half_rn(st[w * 129 + ci]);
    }
}

// ------------------------------- main kernel ---------------------------------
// dynamic smem layout (bytes):
//   A  : [0,     34816)   272 rows x 128B, swizzled
//   B0 : [34816, 51200)   128 rows x 128B, swizzled (double-buffered)
//   B1 : [51200, 67584)
//   D (epilogue, reuses all): 128co x 132 floats = 67584B
#define SM_A     0
#define SM_B0    34816
#define SM_B1    51200
#define SM_TOTAL 67584

__global__ void __launch_bounds__(256, 2)
bconv_hmma(float* __restrict__ out) {
    extern __shared__ char sm[];
    const uint32_t smb = smem_u32(sm);

    const int t    = threadIdx.x;
    const int wid  = t >> 5;
    const int lane = t & 31;
    const int n    = blockIdx.z;
    const int coB  = blockIdx.y;           // 0/1 -> co block of 128
    const int p0   = blockIdx.x * 128;

    const int mw = wid & 1;                // 2 m-halves of 64 pix
    const int nw = wid >> 1;               // 4 n-quarters of 32 co

    // lane-invariant ldmatrix offsets
    const int q  = lane >> 3;
    const int rA = (lane & 7) + ((q & 1) << 3);     // A row-in-tile
    const int cA = q >> 1;                          // A k-half (16B unit)
    const int rB = (lane & 7) + ((lane >> 4) << 3); // B row-in-pair
    const int cB = q & 1;                           // B k-half

    float acc[4][4][4];
#pragma unroll
    for (int i = 0; i < 4; i++)
#pragma unroll
        for (int j = 0; j < 4; j++)
#pragma unroll
            for (int k = 0; k < 4; k++) acc[i][j][k] = 0.f;

    // element offset of halo row 0 (ci0 of current image)
    const size_t xrow0 = ((size_t)n * NPOS_STRIDE + POS_BASE + p0 - HALO) * 128;
    const __half* wbase = g_wb + (coB << 13);   // co block offset

    // ---- prologue: prefetch B(iter 0) ----
    {
        for (int i = t; i < 1024; i += 256) {
            const int r = i >> 3, j = i & 7;
            const uint32_t doff = (uint32_t)(r * 128 + ((j ^ (r & 7)) << 4));
            CP_ASYNC16(smb + SM_B0 + doff, wbase + (i << 3));
        }
        CP_COMMIT();
    }

#pragma unroll 1
    for (int iter = 0; iter < 18; ++iter) {
        const int chunk = iter / 9;
        const int tap   = iter - chunk * 9;

        if (tap == 0) {
            __syncthreads();   // everyone done reading old A halo
            // ---- cp.async A halo: 272 rows x 64 ci, swizzled ----
            for (int i = t; i < A_ROWS * 8; i += 256) {
                const int r = i >> 3, j = i & 7;
                const size_t gsrc = xrow0 + (size_t)r * 128 + (chunk << 6) + (j << 3);
                const uint32_t doff = (uint32_t)(r * 128 + ((j ^ (r & 7)) << 4));
                CP_ASYNC16(smb + SM_A + doff, g_xh + gsrc);
            }
            CP_COMMIT();
        }

        CP_WAIT0();            // A (this chunk) + B (this iter) landed
        __syncthreads();       // also frees the other B buffer for prefetch

        if (iter < 17) {       // ---- prefetch next iter's B ----
            const int ni = iter + 1;
            const int nc = ni / 9;
            const __half* src = wbase + ((nc * 9 + (ni - nc * 9)) << 14);
            const uint32_t bdst = smb + ((ni & 1) ? SM_B1 : SM_B0);
            for (int i = t; i < 1024; i += 256) {
                const int r = i >> 3, j = i & 7;
                const uint32_t doff = (uint32_t)(r * 128 + ((j ^ (r & 7)) << 4));
                CP_ASYNC16(bdst + doff, src + (i << 3));
            }
            CP_COMMIT();
        }

        // ---- compute tap ----
        const int s = (tap / 3 - 1) * 66 + (tap % 3 - 1);
        const int aRowBase = mw * 64 + s + HALO;
        const int bRowBase = nw * 32;
        const uint32_t bbase = smb + ((iter & 1) ? SM_B1 : SM_B0);

#pragma unroll
        for (int ks = 0; ks < 4; ks++) {
            uint32_t bf[4][2];
#pragma unroll
            for (int pr = 0; pr < 2; pr++) {
                const int row = bRowBase + pr * 16 + rB;
                const uint32_t addr = bbase + row * 128 +
                                      (((2 * ks + cB) ^ (row & 7)) << 4);
                ldsm_x4(bf[pr * 2][0], bf[pr * 2][1],
                        bf[pr * 2 + 1][0], bf[pr * 2 + 1][1], addr);
            }
            uint32_t af[4][4];
#pragma unroll
            for (int mt = 0; mt < 4; mt++) {
                const int row = aRowBase + mt * 16 + rA;
                const uint32_t addr = smb + SM_A + row * 128 +
                                      (((2 * ks + cA) ^ (row & 7)) << 4);
                ldsm_x4(af[mt][0], af[mt][1], af[mt][2], af[mt][3], addr);
            }
#pragma unroll
            for (int mt = 0; mt < 4; mt++)
#pragma unroll
                for (int nt = 0; nt < 4; nt++)
                    mma_f16(acc[mt][nt], af[mt], bf[nt][0], bf[nt][1]);
        }
    }

    // ---- epilogue: acc -> smem D [co][132] -> coalesced masked gmem stores ----
    __syncthreads();
    float* D = (float*)sm;
    const int gRow = lane >> 2;
    const int gCol = (lane & 3) * 2;
#pragma unroll
    for (int mt = 0; mt < 4; mt++) {
#pragma unroll
        for (int nt = 0; nt < 4; nt++) {
            const int pl  = mw * 64 + mt * 16 + gRow;
            const int col = nw * 32 + nt * 8 + gCol;
            D[col * 132 + pl]           = acc[mt][nt][0];
            D[(col + 1) * 132 + pl]     = acc[mt][nt][1];
            D[col * 132 + pl + 8]       = acc[mt][nt][2];
            D[(col + 1) * 132 + pl + 8] = acc[mt][nt][3];
        }
    }
    __syncthreads();

    for (int i = t; i < 128 * 128; i += 256) {
        const int co_l = i >> 7, p_l = i & 127;
        const int p  = p0 + p_l;
        const int hp = p / 66;
        const int wp = p - hp * 66;
        if (hp >= 1 && hp <= 64 && wp >= 1 && wp <= 64)
            out[(((size_t)n * 256 + coB * 128 + co_l) << 12) +
                ((hp - 1) << 6) + (wp - 1)] = D[co_l * 132 + p_l];
    }
}

// ------------------------------- launcher ------------------------------------
extern "C" void kernel_launch(void* const* d_in, const int* in_sizes, int n_in,
                              void* d_out, int out_size) {
    const float* x = (const float*)d_in[0];
    const float* w = (const float*)d_in[1];
    float* out = (float*)d_out;

    cudaFuncSetAttribute(bconv_hmma, cudaFuncAttributeMaxDynamicSharedMemorySize,
                         SM_TOTAL);

    prep_w<<<1152, 256>>>(w);
    prep_x<<<dim3(64, 32), 256>>>(x);
    bconv_hmma<<<dim3(N_TILES, 2, 32), 256, SM_TOTAL>>>(out);
}